// round 7
// baseline (speedup 1.0000x reference)
#include <cuda_runtime.h>
#include <cuda_bf16.h>

#define SEQ   2048
#define BATCH 64
#define HID   256
#define G4    1024
#define NCTA  128
#define HS_ELEMS (BATCH*SEQ*HID)

__device__ float    g_xU[(size_t)SEQ * BATCH * G4];
__device__ float    g_hbuf[2][BATCH * HID];
__device__ unsigned g_count;
__device__ unsigned g_gen;

__device__ __forceinline__ float4 ldcg4(const float4* p) {
    float4 v;
    asm volatile("ld.global.cg.v4.f32 {%0,%1,%2,%3}, [%4];"
                 : "=f"(v.x), "=f"(v.y), "=f"(v.z), "=f"(v.w) : "l"(p));
    return v;
}

__device__ __forceinline__ void grid_barrier() {
    __syncthreads();
    if (threadIdx.x == 0) {
        unsigned target = *((volatile unsigned*)&g_gen) + 1u;
        __threadfence();
        unsigned t = atomicAdd(&g_count, 1u);
        if (t == NCTA - 1u) {
            atomicExch(&g_count, 0u);
            __threadfence();
            atomicAdd(&g_gen, 1u);
        } else {
            while (*((volatile unsigned*)&g_gen) != target) { __nanosleep(32); }
        }
        __threadfence();
    }
    __syncthreads();
}

__device__ __forceinline__ float sigf(float x)     { return 1.f / (1.f + __expf(-x)); }
__device__ __forceinline__ float tanhfast(float x) { return 1.f - 2.f / (__expf(2.f * x) + 1.f); }

// ---- kernel 1: xU GEMM. grid (16 colblocks, 2048 t), 256 thr, 64x64 tile ----
__global__ void __launch_bounds__(256) xu_gemm(
    const float* __restrict__ x,
    const float* __restrict__ U0, const float* __restrict__ U1,
    const float* __restrict__ U2, const float* __restrict__ U3,
    const float* __restrict__ B0, const float* __restrict__ B1,
    const float* __restrict__ B2, const float* __restrict__ B3)
{
    __shared__ float As[16][68];
    __shared__ float Bs[16][64];

    const int t     = blockIdx.y;
    const int nb    = blockIdx.x;
    const int gate  = nb >> 2;
    const int ucol0 = (nb & 3) * 64;
    const float* U  = (gate == 0) ? U0 : (gate == 1) ? U1 : (gate == 2) ? U2 : U3;
    const float* Bb = (gate == 0) ? B0 : (gate == 1) ? B1 : (gate == 2) ? B2 : B3;

    const int tid  = threadIdx.x;
    const int ty   = tid >> 4;
    const int tx   = tid & 15;
    const int bRow = tid >> 2;
    const int kq   = (tid & 3) << 2;
    const int kRow = tid >> 4;
    const int n4   = (tid & 15) << 2;

    const float* xrow = x + ((size_t)bRow * SEQ + t) * 256;
    float acc[4][4] = {};

    for (int kb = 0; kb < 256; kb += 16) {
        float4 xa = *(const float4*)(xrow + kb + kq);
        As[kq + 0][bRow] = xa.x;
        As[kq + 1][bRow] = xa.y;
        As[kq + 2][bRow] = xa.z;
        As[kq + 3][bRow] = xa.w;
        *(float4*)&Bs[kRow][n4] = *(const float4*)(U + (size_t)(kb + kRow) * 256 + ucol0 + n4);
        __syncthreads();
#pragma unroll
        for (int kk = 0; kk < 16; ++kk) {
            float4 a = *(float4*)&As[kk][ty * 4];
            float4 b = *(float4*)&Bs[kk][tx * 4];
            float av[4] = {a.x, a.y, a.z, a.w};
            float bv[4] = {b.x, b.y, b.z, b.w};
#pragma unroll
            for (int i = 0; i < 4; ++i)
#pragma unroll
                for (int j = 0; j < 4; ++j)
                    acc[i][j] += av[i] * bv[j];
        }
        __syncthreads();
    }

    float4 bv4 = *(const float4*)(Bb + ucol0 + tx * 4);
    float bb[4] = {bv4.x, bv4.y, bv4.z, bv4.w};
#pragma unroll
    for (int i = 0; i < 4; ++i) {
        int row = t * BATCH + ty * 4 + i;
        float4 o;
        o.x = acc[i][0] + bb[0];
        o.y = acc[i][1] + bb[1];
        o.z = acc[i][2] + bb[2];
        o.w = acc[i][3] + bb[3];
        *(float4*)&g_xU[(size_t)row * G4 + nb * 64 + tx * 4] = o;
    }
}

// ---- kernel 2: persistent recurrence, 128 CTAs x 256 thr ----
#define REC_SMEM_FLOATS (64*260 + 8*260 + 512 + 512)

__global__ void __launch_bounds__(256, 1) lstm_rec(
    const float* __restrict__ V0, const float* __restrict__ V1,
    const float* __restrict__ V2, const float* __restrict__ V3,
    float* __restrict__ out, int write_final)
{
    extern __shared__ float sm[];
    float* h_s = sm;                 // [64][260]
    float* vt  = sm + 64 * 260;      // [8][260]
    float* z_s = vt + 8 * 260;       // [64][8]
    float* red = z_s + 512;          // [128][4]

    const int tid = threadIdx.x;
    const int ci  = blockIdx.x;
    const int u0  = ci * 2;

    for (int i = tid; i < 2048; i += 256) {
        int c = i >> 8, k = i & 255;
        int g = c >> 1, j = c & 1;
        const float* Vg = (g == 0) ? V0 : (g == 1) ? V1 : (g == 2) ? V2 : V3;
        vt[c * 260 + k] = Vg[k * 256 + u0 + j];
    }

    const int ks = tid >> 7;
    const int r  = tid & 127;
    const int bp = r >> 2;
    const int g  = r & 3;
    const int bA = bp, bB = bp + 32;
    const int k0 = ks << 7;
    const int eb = tid >> 1;
    const int ej = tid & 1;
    float c_state = 0.f;

    if (tid < 128) g_hbuf[0][eb * HID + u0 + ej] = 0.f;
    __threadfence();
    grid_barrier();

    const float* vp0 = vt + (2 * g) * 260 + k0;
    const float* vp1 = vp0 + 260;
    const float* hAp = h_s + bA * 260 + k0;
    const float* hBp = h_s + bB * 260 + k0;
    const float* xuA = g_xU + bA * G4 + g * 256 + u0;
    const float* xuB = g_xU + bB * G4 + g * 256 + u0;

    for (int t = 0; t < SEQ; ++t) {
        const int pr = t & 1, pw = pr ^ 1;

        const float* hg = g_hbuf[pr];
        for (int q = tid; q < 4096; q += 256) {
            int b = q >> 6, k4 = (q & 63) << 2;
            float4 v = ldcg4((const float4*)(hg + b * 256 + k4));
            *(float4*)&h_s[b * 260 + k4] = v;
        }
        __syncthreads();

        float2 xA = make_float2(0.f, 0.f), xB = make_float2(0.f, 0.f);
        if (ks == 0) {
            xA = *(const float2*)(xuA + (size_t)t * BATCH * G4);
            xB = *(const float2*)(xuB + (size_t)t * BATCH * G4);
        }

        float a00 = 0.f, a01 = 0.f, a10 = 0.f, a11 = 0.f;
#pragma unroll 4
        for (int k = 0; k < 128; k += 4) {
            float4 ha = *(const float4*)(hAp + k);
            float4 hb = *(const float4*)(hBp + k);
            float4 v0 = *(const float4*)(vp0 + k);
            float4 v1 = *(const float4*)(vp1 + k);
            a00 += ha.x * v0.x; a01 += ha.x * v1.x; a10 += hb.x * v0.x; a11 += hb.x * v1.x;
            a00 += ha.y * v0.y; a01 += ha.y * v1.y; a10 += hb.y * v0.y; a11 += hb.y * v1.y;
            a00 += ha.z * v0.z; a01 += ha.z * v1.z; a10 += hb.z * v0.z; a11 += hb.z * v1.z;
            a00 += ha.w * v0.w; a01 += ha.w * v1.w; a10 += hb.w * v0.w; a11 += hb.w * v1.w;
        }

        if (ks == 1)
            *(float4*)&red[r * 4] = make_float4(a00, a01, a10, a11);
        __syncthreads();
        if (ks == 0) {
            float4 p = *(float4*)&red[r * 4];
            *(float2*)&z_s[bA * 8 + 2 * g] = make_float2(a00 + p.x + xA.x, a01 + p.y + xA.y);
            *(float2*)&z_s[bB * 8 + 2 * g] = make_float2(a10 + p.z + xB.x, a11 + p.w + xB.y);
        }
        __syncthreads();

        if (tid < 128) {
            float zi = z_s[eb * 8 + 0 + ej];
            float zf = z_s[eb * 8 + 2 + ej];
            float zo = z_s[eb * 8 + 4 + ej];
            float zg = z_s[eb * 8 + 6 + ej];
            float ig = sigf(zi), fg = sigf(zf), og = sigf(zo), gg = tanhfast(zg);
            c_state = fg * c_state + ig * gg;
            float h = og * tanhfast(c_state);
            int u = u0 + ej;
            g_hbuf[pw][eb * HID + u] = h;
            out[((size_t)eb * SEQ + t) * HID + u] = h;
            if (write_final && t == SEQ - 1) {
                out[(size_t)HS_ELEMS + eb * HID + u]               = h;
                out[(size_t)HS_ELEMS + BATCH * HID + eb * HID + u] = c_state;
            }
            __threadfence();
        }
        grid_barrier();
    }
}

extern "C" void kernel_launch(void* const* d_in, const int* in_sizes, int n_in,
                              void* d_out, int out_size) {
    const float* x  = (const float*)d_in[0];
    const float* Ui = (const float*)d_in[1];
    const float* Vi = (const float*)d_in[2];
    const float* bi = (const float*)d_in[3];
    const float* Uf = (const float*)d_in[4];
    const float* Vf = (const float*)d_in[5];
    const float* bf = (const float*)d_in[6];
    const float* Uo = (const float*)d_in[7];
    const float* Vo = (const float*)d_in[8];
    const float* bo = (const float*)d_in[9];
    const float* Uc = (const float*)d_in[10];
    const float* Vc = (const float*)d_in[11];
    const float* bc = (const float*)d_in[12];
    float* out = (float*)d_out;

    static int smem_set = 0;
    if (!smem_set) {
        cudaFuncSetAttribute(lstm_rec, cudaFuncAttributeMaxDynamicSharedMemorySize,
                             REC_SMEM_FLOATS * (int)sizeof(float));
        smem_set = 1;
    }

    dim3 ggrid(16, SEQ);
    xu_gemm<<<ggrid, 256>>>(x, Ui, Uf, Uo, Uc, bi, bf, bo, bc);

    int write_final = (out_size >= HS_ELEMS + 2 * BATCH * HID) ? 1 : 0;
    lstm_rec<<<NCTA, 256, REC_SMEM_FLOATS * (int)sizeof(float)>>>(
        Vi, Vf, Vo, Vc, out, write_final);
}

// round 8
// speedup vs baseline: 1.0511x; 1.0511x over previous
#include <cuda_runtime.h>
#include <cuda_bf16.h>

#define SEQ   2048
#define BATCH 64
#define HID   256
#define G4    1024
#define NCTA  128
#define HS_ELEMS (BATCH*SEQ*HID)

#define VT_LD  132              // vt row: 128 cols + 4 pad
#define HS_LD  260
#define RED_LD 516              // 512 + 4 pad
#define SM_H   (256*VT_LD)                  // 33792 floats
#define SM_RED (SM_H + 4*HS_LD)             // +1040
#define SM_TOT (SM_RED + 8*RED_LD)          // +4128 = 38960 floats (~156 KB)

__device__ float    g_xU[(size_t)SEQ * BATCH * G4];
__device__ float    g_hbuf[2][BATCH * HID];
__device__ unsigned g_count;
__device__ unsigned g_gen;

__device__ __forceinline__ float4 ldcg4(const float4* p) {
    float4 v;
    asm volatile("ld.global.cg.v4.f32 {%0,%1,%2,%3}, [%4];"
                 : "=f"(v.x), "=f"(v.y), "=f"(v.z), "=f"(v.w) : "l"(p));
    return v;
}

__device__ __forceinline__ void grid_barrier() {
    __syncthreads();
    if (threadIdx.x == 0) {
        unsigned target = *((volatile unsigned*)&g_gen) + 1u;
        unsigned t = atomicAdd(&g_count, 1u);
        if (t == NCTA - 1u) {
            atomicExch(&g_count, 0u);
            __threadfence();
            atomicAdd(&g_gen, 1u);
        } else {
            while (*((volatile unsigned*)&g_gen) != target) {}
        }
        __threadfence();
    }
    __syncthreads();
}

__device__ __forceinline__ float sigf(float x)     { return 1.f / (1.f + __expf(-x)); }
__device__ __forceinline__ float tanhfast(float x) { return 1.f - 2.f / (__expf(2.f * x) + 1.f); }

// ---- kernel 1: xU GEMM (unchanged). grid (16, 2048), 256 thr, 64x64 tile ----
__global__ void __launch_bounds__(256) xu_gemm(
    const float* __restrict__ x,
    const float* __restrict__ U0, const float* __restrict__ U1,
    const float* __restrict__ U2, const float* __restrict__ U3,
    const float* __restrict__ B0, const float* __restrict__ B1,
    const float* __restrict__ B2, const float* __restrict__ B3)
{
    __shared__ float As[16][68];
    __shared__ float Bs[16][64];

    const int t     = blockIdx.y;
    const int nb    = blockIdx.x;
    const int gate  = nb >> 2;
    const int ucol0 = (nb & 3) * 64;
    const float* U  = (gate == 0) ? U0 : (gate == 1) ? U1 : (gate == 2) ? U2 : U3;
    const float* Bb = (gate == 0) ? B0 : (gate == 1) ? B1 : (gate == 2) ? B2 : B3;

    const int tid  = threadIdx.x;
    const int ty   = tid >> 4;
    const int tx   = tid & 15;
    const int bRow = tid >> 2;
    const int kq   = (tid & 3) << 2;
    const int kRow = tid >> 4;
    const int n4   = (tid & 15) << 2;

    const float* xrow = x + ((size_t)bRow * SEQ + t) * 256;
    float acc[4][4] = {};

    for (int kb = 0; kb < 256; kb += 16) {
        float4 xa = *(const float4*)(xrow + kb + kq);
        As[kq + 0][bRow] = xa.x;
        As[kq + 1][bRow] = xa.y;
        As[kq + 2][bRow] = xa.z;
        As[kq + 3][bRow] = xa.w;
        *(float4*)&Bs[kRow][n4] = *(const float4*)(U + (size_t)(kb + kRow) * 256 + ucol0 + n4);
        __syncthreads();
#pragma unroll
        for (int kk = 0; kk < 16; ++kk) {
            float4 a = *(float4*)&As[kk][ty * 4];
            float4 b = *(float4*)&Bs[kk][tx * 4];
            float av[4] = {a.x, a.y, a.z, a.w};
            float bv[4] = {b.x, b.y, b.z, b.w};
#pragma unroll
            for (int i = 0; i < 4; ++i)
#pragma unroll
                for (int j = 0; j < 4; ++j)
                    acc[i][j] += av[i] * bv[j];
        }
        __syncthreads();
    }

    float4 bv4 = *(const float4*)(Bb + ucol0 + tx * 4);
    float bb[4] = {bv4.x, bv4.y, bv4.z, bv4.w};
#pragma unroll
    for (int i = 0; i < 4; ++i) {
        int row = t * BATCH + ty * 4 + i;
        float4 o;
        o.x = acc[i][0] + bb[0];
        o.y = acc[i][1] + bb[1];
        o.z = acc[i][2] + bb[2];
        o.w = acc[i][3] + bb[3];
        *(float4*)&g_xU[(size_t)row * G4 + nb * 64 + tx * 4] = o;
    }
}

// ---- kernel 2: persistent recurrence, 128 CTAs = 16 batch-groups x 8 col-groups ----
__global__ void __launch_bounds__(256, 1) lstm_rec(
    const float* __restrict__ V0, const float* __restrict__ V1,
    const float* __restrict__ V2, const float* __restrict__ V3,
    float* __restrict__ out, int write_final)
{
    extern __shared__ float sm[];
    float* vt  = sm;                 // [256][VT_LD]  V slice, vt[k][c], c = g*32+ul
    float* h_s = sm + SM_H;          // [4][HS_LD]
    float* red = sm + SM_RED;        // [8][RED_LD]

    const int tid = threadIdx.x;
    const int ci  = blockIdx.x;
    const int bg  = ci >> 3;         // batch-group 0..15
    const int cg  = ci & 7;          // col-group  0..7
    const int b0  = bg * 4;
    const int u0  = cg * 32;

    // fill V slice: vt[k][g*32+ul] = Vg[k][u0+ul]
    for (int i = tid; i < 256 * 128; i += 256) {
        int k = i >> 7, c = i & 127;
        int g = c >> 5, ul = c & 31;
        const float* Vg = (g == 0) ? V0 : (g == 1) ? V1 : (g == 2) ? V2 : V3;
        vt[k * VT_LD + c] = Vg[k * 256 + u0 + ul];
    }

    // init h0 = 0 for our batch rows (cg==0 CTA of each batch-group)
    if (cg == 0)
        for (int i = tid; i < 4 * 256; i += 256)
            g_hbuf[0][b0 * 256 + i] = 0.f;
    __threadfence();
    grid_barrier();

    // compute mapping: warp ks = tid>>5 owns K slice [ks*32, ks*32+32); lane cc owns cols 4cc..4cc+3
    const int ks    = tid >> 5;
    const int cc    = tid & 31;
    const int c0    = cc * 4;
    const int kbase = ks * 32;
    // epilogue mapping (tid < 128): batch eb, unit ul
    const int eb = tid >> 5;
    const int ul = tid & 31;
    float c_state = 0.f;

    const float* vbase = vt + kbase * VT_LD + c0;

    for (int t = 0; t < SEQ; ++t) {
        const int pr = t & 1, pw = pr ^ 1;

        // prefetch xU for this step (consumed in epilogue, ~2k cyc later)
        float xu0 = 0.f, xu1 = 0.f, xu2 = 0.f, xu3 = 0.f;
        if (tid < 128) {
            const float* xp = g_xU + ((size_t)t * BATCH + b0 + eb) * G4 + u0 + ul;
            xu0 = xp[0]; xu1 = xp[256]; xu2 = xp[512]; xu3 = xp[768];
        }

        // load h slice: 4 batches x 256 = 4KB, one float4 per thread
        {
            int b = tid >> 6, k4 = (tid & 63) << 2;
            float4 v = ldcg4((const float4*)(g_hbuf[pr] + (b0 + b) * 256 + k4));
            *(float4*)&h_s[b * HS_LD + k4] = v;
        }
        __syncthreads();

        // dot: acc[b][j] over k in [kbase, kbase+32)
        float acc[4][4] = {};
#pragma unroll
        for (int kk = 0; kk < 32; kk += 4) {
            float4 h0v = *(const float4*)&h_s[0 * HS_LD + kbase + kk];
            float4 h1v = *(const float4*)&h_s[1 * HS_LD + kbase + kk];
            float4 h2v = *(const float4*)&h_s[2 * HS_LD + kbase + kk];
            float4 h3v = *(const float4*)&h_s[3 * HS_LD + kbase + kk];
            const float* vp = vbase + kk * VT_LD;
            float4 va = *(const float4*)(vp);
            float4 vb = *(const float4*)(vp + VT_LD);
            float4 vc = *(const float4*)(vp + 2 * VT_LD);
            float4 vd = *(const float4*)(vp + 3 * VT_LD);
#define MAC4(hb, b) \
            acc[b][0] += hb.x*va.x + hb.y*vb.x + hb.z*vc.x + hb.w*vd.x; \
            acc[b][1] += hb.x*va.y + hb.y*vb.y + hb.z*vc.y + hb.w*vd.y; \
            acc[b][2] += hb.x*va.z + hb.y*vb.z + hb.z*vc.z + hb.w*vd.z; \
            acc[b][3] += hb.x*va.w + hb.y*vb.w + hb.z*vc.w + hb.w*vd.w;
            MAC4(h0v, 0) MAC4(h1v, 1) MAC4(h2v, 2) MAC4(h3v, 3)
#undef MAC4
        }

        // store K partials: red[ks][b*128 + c0..c0+3]
        {
            float* rp = red + ks * RED_LD + c0;
            *(float4*)&rp[0 * 128] = make_float4(acc[0][0], acc[0][1], acc[0][2], acc[0][3]);
            *(float4*)&rp[1 * 128] = make_float4(acc[1][0], acc[1][1], acc[1][2], acc[1][3]);
            *(float4*)&rp[2 * 128] = make_float4(acc[2][0], acc[2][1], acc[2][2], acc[2][3]);
            *(float4*)&rp[3 * 128] = make_float4(acc[3][0], acc[3][1], acc[3][2], acc[3][3]);
        }
        __syncthreads();

        // epilogue: 128 threads, one (batch, unit) each
        if (tid < 128) {
            float z0 = xu0, z1 = xu1, z2 = xu2, z3 = xu3;
            int base = eb * 128 + ul;
#pragma unroll
            for (int s = 0; s < 8; ++s) {
                const float* rr = red + s * RED_LD + base;
                z0 += rr[0]; z1 += rr[32]; z2 += rr[64]; z3 += rr[96];
            }
            float ig = sigf(z0), fg = sigf(z1), og = sigf(z2), gg = tanhfast(z3);
            c_state = fg * c_state + ig * gg;
            float h = og * tanhfast(c_state);
            int b = b0 + eb, u = u0 + ul;
            g_hbuf[pw][b * 256 + u] = h;
            out[((size_t)b * SEQ + t) * HID + u] = h;
            if (write_final && t == SEQ - 1) {
                out[(size_t)HS_ELEMS + b * HID + u]               = h;
                out[(size_t)HS_ELEMS + BATCH * HID + b * HID + u] = c_state;
            }
            __threadfence();
        }
        grid_barrier();
    }
}

extern "C" void kernel_launch(void* const* d_in, const int* in_sizes, int n_in,
                              void* d_out, int out_size) {
    const float* x  = (const float*)d_in[0];
    const float* Ui = (const float*)d_in[1];
    const float* Vi = (const float*)d_in[2];
    const float* Uf = (const float*)d_in[4];
    const float* Vf = (const float*)d_in[5];
    const float* Uo = (const float*)d_in[7];
    const float* Vo = (const float*)d_in[8];
    const float* Uc = (const float*)d_in[10];
    const float* Vc = (const float*)d_in[11];
    const float* bi = (const float*)d_in[3];
    const float* bf = (const float*)d_in[6];
    const float* bo = (const float*)d_in[9];
    const float* bc = (const float*)d_in[12];
    float* out = (float*)d_out;

    static int smem_set = 0;
    if (!smem_set) {
        cudaFuncSetAttribute(lstm_rec, cudaFuncAttributeMaxDynamicSharedMemorySize,
                             SM_TOT * (int)sizeof(float));
        smem_set = 1;
    }

    dim3 ggrid(16, SEQ);
    xu_gemm<<<ggrid, 256>>>(x, Ui, Uf, Uo, Uc, bi, bf, bo, bc);

    int write_final = (out_size >= HS_ELEMS + 2 * BATCH * HID) ? 1 : 0;
    lstm_rec<<<NCTA, 256, SM_TOT * (int)sizeof(float)>>>(Vi, Vf, Vo, Vc, out, write_final);
}

// round 13
// speedup vs baseline: 1.9770x; 1.8809x over previous
#include <cuda_runtime.h>
#include <cuda_bf16.h>
#include <cstdint>

#define SEQ   2048
#define BATCH 64
#define HID   256
#define G4    1024
#define NCTA  128
#define NGRP  16
#define HS_ELEMS (BATCH*SEQ*HID)

#define VT_LD  132
#define HS_LD  260
#define RED_LD 516
#define SM_VT  0
#define SM_H   (256*VT_LD)                    // 33792
#define SM_RED (SM_H + 4*HS_LD)               // +1040 = 34832
#define SM_TOT (SM_RED + 8*RED_LD)            // +4128 = 38960 floats (~156 KB)

__device__ float    g_xU[(size_t)SEQ * BATCH * G4];
__device__ float    g_hbuf[2][BATCH * HID];
__device__ unsigned g_flag[NGRP][8 * 32];     // one 128B line per (group, cg)
__device__ unsigned g_icount[NGRP];
__device__ unsigned g_igen[NGRP];

__device__ __forceinline__ float4 ldcg4(const float4* p) {
    float4 v;
    asm volatile("ld.global.cg.v4.f32 {%0,%1,%2,%3}, [%4];"
                 : "=f"(v.x), "=f"(v.y), "=f"(v.z), "=f"(v.w) : "l"(p));
    return v;
}
// morally-strong scoped flag ops (the R12 bug fix)
__device__ __forceinline__ unsigned ld_acquire_u32(const unsigned* p) {
    unsigned v;
    asm volatile("ld.acquire.gpu.global.u32 %0, [%1];" : "=r"(v) : "l"(p) : "memory");
    return v;
}
__device__ __forceinline__ void st_release_u32(unsigned* p, unsigned v) {
    asm volatile("st.release.gpu.global.u32 [%0], %1;" :: "l"(p), "r"(v) : "memory");
}
__device__ __forceinline__ void st_relaxed_u32(unsigned* p, unsigned v) {
    asm volatile("st.relaxed.gpu.global.u32 [%0], %1;" :: "l"(p), "r"(v) : "memory");
}
__device__ __forceinline__ void stcg_f32(float* p, float v) {
    asm volatile("st.global.cg.f32 [%0], %1;" :: "l"(p), "f"(v) : "memory");
}

__device__ __forceinline__ float sigf(float x)     { return 1.f / (1.f + __expf(-x)); }
__device__ __forceinline__ float tanhfast(float x) { return 1.f - 2.f / (__expf(2.f * x) + 1.f); }

// ---- kernel 1: xU GEMM (proven in R7/R8). grid (16, 2048), 256 thr ----
__global__ void __launch_bounds__(256) xu_gemm(
    const float* __restrict__ x,
    const float* __restrict__ U0, const float* __restrict__ U1,
    const float* __restrict__ U2, const float* __restrict__ U3,
    const float* __restrict__ B0, const float* __restrict__ B1,
    const float* __restrict__ B2, const float* __restrict__ B3)
{
    __shared__ float As[16][68];
    __shared__ float Bs[16][64];

    const int t     = blockIdx.y;
    const int nb    = blockIdx.x;
    const int gate  = nb >> 2;
    const int ucol0 = (nb & 3) * 64;
    const float* U  = (gate == 0) ? U0 : (gate == 1) ? U1 : (gate == 2) ? U2 : U3;
    const float* Bb = (gate == 0) ? B0 : (gate == 1) ? B1 : (gate == 2) ? B2 : B3;

    const int tid  = threadIdx.x;
    const int ty   = tid >> 4;
    const int tx   = tid & 15;
    const int bRow = tid >> 2;
    const int kq   = (tid & 3) << 2;
    const int kRow = tid >> 4;
    const int n4   = (tid & 15) << 2;

    const float* xrow = x + ((size_t)bRow * SEQ + t) * 256;
    float acc[4][4] = {};

    for (int kb = 0; kb < 256; kb += 16) {
        float4 xa = *(const float4*)(xrow + kb + kq);
        As[kq + 0][bRow] = xa.x;
        As[kq + 1][bRow] = xa.y;
        As[kq + 2][bRow] = xa.z;
        As[kq + 3][bRow] = xa.w;
        *(float4*)&Bs[kRow][n4] = *(const float4*)(U + (size_t)(kb + kRow) * 256 + ucol0 + n4);
        __syncthreads();
#pragma unroll
        for (int kk = 0; kk < 16; ++kk) {
            float4 a = *(float4*)&As[kk][ty * 4];
            float4 b = *(float4*)&Bs[kk][tx * 4];
            float av[4] = {a.x, a.y, a.z, a.w};
            float bv[4] = {b.x, b.y, b.z, b.w};
#pragma unroll
            for (int i = 0; i < 4; ++i)
#pragma unroll
                for (int j = 0; j < 4; ++j)
                    acc[i][j] += av[i] * bv[j];
        }
        __syncthreads();
    }

    float4 bv4 = *(const float4*)(Bb + ucol0 + tx * 4);
    float bb[4] = {bv4.x, bv4.y, bv4.z, bv4.w};
#pragma unroll
    for (int i = 0; i < 4; ++i) {
        int row = t * BATCH + ty * 4 + i;
        float4 o;
        o.x = acc[i][0] + bb[0];
        o.y = acc[i][1] + bb[1];
        o.z = acc[i][2] + bb[2];
        o.w = acc[i][3] + bb[3];
        *(float4*)&g_xU[(size_t)row * G4 + nb * 64 + tx * 4] = o;
    }
}

// ---- kernel 2: recurrence. 128 CTAs = 16 groups x 8; group-local flag barrier ----
__global__ void __launch_bounds__(256, 1) lstm_rec(
    const float* __restrict__ V0, const float* __restrict__ V1,
    const float* __restrict__ V2, const float* __restrict__ V3,
    float* __restrict__ out, int write_final)
{
    extern __shared__ float sm[];
    float* vt  = sm + SM_VT;     // [256][VT_LD]  vt[k][c], c = g*32+ul
    float* h_s = sm + SM_H;      // [4][HS_LD]
    float* red = sm + SM_RED;    // [8][RED_LD]

    const int tid = threadIdx.x;
    const int ci  = blockIdx.x;
    const int bg  = ci >> 3;
    const int cg  = ci & 7;
    const int b0  = bg * 4;
    const int u0  = cg * 32;

    // V slice
    for (int i = tid; i < 256 * 128; i += 256) {
        int k = i >> 7, c = i & 127;
        int g = c >> 5, ul = c & 31;
        const float* Vg = (g == 0) ? V0 : (g == 1) ? V1 : (g == 2) ? V2 : V3;
        vt[k * VT_LD + c] = Vg[k * 256 + u0 + ul];
    }

    // --- replay-safe init: reset own flag, zero h buffer 0, then group barrier ---
    if (tid == 0) st_relaxed_u32(&g_flag[bg][cg * 32], 0u);
    if (cg == 0)
        for (int i = tid; i < 4 * 256; i += 256)
            g_hbuf[0][b0 * 256 + i] = 0.f;
    __threadfence();
    __syncthreads();
    if (tid == 0) {
        unsigned target = atomicAdd(&g_igen[bg], 0u) + 1u;   // strong read
        unsigned a = atomicAdd(&g_icount[bg], 1u);
        if (a == 7u) {
            atomicExch(&g_icount[bg], 0u);
            __threadfence();
            atomicAdd(&g_igen[bg], 1u);
        } else {
            while (atomicAdd(&g_igen[bg], 0u) != target) {}
        }
        __threadfence();
    }
    __syncthreads();

    // mappings (identical to R8)
    const int ks    = tid >> 5;
    const int cc    = tid & 31;
    const int c0    = cc * 4;
    const int kbase = ks * 32;
    const int eb = tid >> 5;       // epilogue (tid<128)
    const int ul = tid & 31;
    float c_state = 0.f;

    const float* vbase = vt + kbase * VT_LD + c0;

    for (int t = 0; t < SEQ; ++t) {
        const int pr = t & 1, pw = pr ^ 1;

        // wait for peers' h of step t-1 (acquire; none needed at t=0)
        if (t > 0) {
            if (tid < 8) {
                const unsigned* fp = &g_flag[bg][tid * 32];
                while (ld_acquire_u32(fp) < (unsigned)t) {}
            }
            __syncthreads();
        }

        // prefetch xU for this step
        float xu0 = 0.f, xu1 = 0.f, xu2 = 0.f, xu3 = 0.f;
        if (tid < 128) {
            const float* xp = g_xU + ((size_t)t * BATCH + b0 + eb) * G4 + u0 + ul;
            xu0 = __ldg(xp); xu1 = __ldg(xp + 256); xu2 = __ldg(xp + 512); xu3 = __ldg(xp + 768);
        }

        // stage h slice (4 batches x 256 = 4KB) into smem
        {
            int b = tid >> 6, k4 = (tid & 63) << 2;
            float4 v = ldcg4((const float4*)(g_hbuf[pr] + (b0 + b) * 256 + k4));
            *(float4*)&h_s[b * HS_LD + k4] = v;
        }
        __syncthreads();

        // dot over k in [kbase, kbase+32)
        float acc[4][4] = {};
#pragma unroll
        for (int kk = 0; kk < 32; kk += 4) {
            float4 h0v = *(const float4*)&h_s[0 * HS_LD + kbase + kk];
            float4 h1v = *(const float4*)&h_s[1 * HS_LD + kbase + kk];
            float4 h2v = *(const float4*)&h_s[2 * HS_LD + kbase + kk];
            float4 h3v = *(const float4*)&h_s[3 * HS_LD + kbase + kk];
            const float* vp = vbase + kk * VT_LD;
            float4 va = *(const float4*)(vp);
            float4 vb = *(const float4*)(vp + VT_LD);
            float4 vc = *(const float4*)(vp + 2 * VT_LD);
            float4 vd = *(const float4*)(vp + 3 * VT_LD);
#define MAC4(hb, b) \
            acc[b][0] += hb.x*va.x + hb.y*vb.x + hb.z*vc.x + hb.w*vd.x; \
            acc[b][1] += hb.x*va.y + hb.y*vb.y + hb.z*vc.y + hb.w*vd.y; \
            acc[b][2] += hb.x*va.z + hb.y*vb.z + hb.z*vc.z + hb.w*vd.z; \
            acc[b][3] += hb.x*va.w + hb.y*vb.w + hb.z*vc.w + hb.w*vd.w;
            MAC4(h0v, 0) MAC4(h1v, 1) MAC4(h2v, 2) MAC4(h3v, 3)
#undef MAC4
        }

        // K partials
        {
            float* rp = red + ks * RED_LD + c0;
            *(float4*)&rp[0 * 128] = make_float4(acc[0][0], acc[0][1], acc[0][2], acc[0][3]);
            *(float4*)&rp[1 * 128] = make_float4(acc[1][0], acc[1][1], acc[1][2], acc[1][3]);
            *(float4*)&rp[2 * 128] = make_float4(acc[2][0], acc[2][1], acc[2][2], acc[2][3]);
            *(float4*)&rp[3 * 128] = make_float4(acc[3][0], acc[3][1], acc[3][2], acc[3][3]);
        }
        __syncthreads();

        // epilogue
        if (tid < 128) {
            float z0 = xu0, z1 = xu1, z2 = xu2, z3 = xu3;
            int base = eb * 128 + ul;
#pragma unroll
            for (int s = 0; s < 8; ++s) {
                const float* rr = red + s * RED_LD + base;
                z0 += rr[0]; z1 += rr[32]; z2 += rr[64]; z3 += rr[96];
            }
            float ig = sigf(z0), fg = sigf(z1), og = sigf(z2), gg = tanhfast(z3);
            c_state = fg * c_state + ig * gg;
            float h = og * tanhfast(c_state);
            int b = b0 + eb, u = u0 + ul;
            stcg_f32(&g_hbuf[pw][b * 256 + u], h);
            out[((size_t)b * SEQ + t) * HID + u] = h;
            if (write_final && t == SEQ - 1) {
                out[(size_t)HS_ELEMS + b * HID + u]               = h;
                out[(size_t)HS_ELEMS + BATCH * HID + b * HID + u] = c_state;
            }
            __threadfence();   // h stores globally visible before barrier arrival
        }
        __syncthreads();
        if (tid == 0) st_release_u32(&g_flag[bg][cg * 32], (unsigned)(t + 1));
    }
}

extern "C" void kernel_launch(void* const* d_in, const int* in_sizes, int n_in,
                              void* d_out, int out_size) {
    const float* x  = (const float*)d_in[0];
    const float* Ui = (const float*)d_in[1];
    const float* Vi = (const float*)d_in[2];
    const float* bi = (const float*)d_in[3];
    const float* Uf = (const float*)d_in[4];
    const float* Vf = (const float*)d_in[5];
    const float* bf = (const float*)d_in[6];
    const float* Uo = (const float*)d_in[7];
    const float* Vo = (const float*)d_in[8];
    const float* bo = (const float*)d_in[9];
    const float* Uc = (const float*)d_in[10];
    const float* Vc = (const float*)d_in[11];
    const float* bc = (const float*)d_in[12];
    float* out = (float*)d_out;

    static int smem_set = 0;
    if (!smem_set) {
        cudaFuncSetAttribute(lstm_rec, cudaFuncAttributeMaxDynamicSharedMemorySize,
                             SM_TOT * (int)sizeof(float));
        smem_set = 1;
    }

    dim3 ggrid(16, SEQ);
    xu_gemm<<<ggrid, 256>>>(x, Ui, Uf, Uo, Uc, bi, bf, bo, bc);

    int write_final = (out_size >= HS_ELEMS + 2 * BATCH * HID) ? 1 : 0;
    lstm_rec<<<NCTA, 256, SM_TOT * (int)sizeof(float)>>>(Vi, Vf, Vo, Vc, out, write_final);
}